// round 9
// baseline (speedup 1.0000x reference)
#include <cuda_runtime.h>
#include <cuda_fp16.h>
#include <cstdint>
#include <math.h>

#define T_LEN 256
#define B_DIM 512
#define F_DIM 256
#define H_DIM 512
#define P_INT 12
#define KTOT  768
#define NG    2048
#define NW    22

// ---------------- GEMM tiling ----------------
#define BM 128
#define BN 128
#define BK 64
#define STG 3
#define NCH (KTOT / BK)

#define A_SZ (BM * BK * 2)
#define B_SZ (BN * BK * 2)
#define SMEM_BYTES (STG * (A_SZ + B_SZ))  // 96 KB

#define WAVE_ROWS (P_INT * B_DIM)
#define WAVE_S ((size_t)WAVE_ROWS * NG)
#define NMT_MAX 48

// tasks per full wave: 12 chainrow + 768 gemm + 768 pw = 1548
#define NTASK_WAVE 1548
#define FULL_TASKS (21 * NTASK_WAVE)        // 32508
#define LAST_CR 4
#define LAST_G  64                           // mtiles 12..15 only
#define LAST_PW 64                           // j==3 blocks only
#define TOTAL_TASKS (FULL_TASKS + LAST_CR + LAST_G + LAST_PW)

// ---------------- static device scratch ----------------
__device__ __half d_Wh[NG * KTOT];
__device__ float  d_Bcat[NG];
__device__ __half d_Xh[T_LEN * B_DIM * F_DIM];
__device__ __half d_Hh[P_INT * B_DIM * H_DIM];
__device__ __half d_Sbuf[2 * WAVE_S];
__device__ float  d_Schain[2 * P_INT * NG];    // chain-row gates, fp32, dbl-buffered
__device__ float  d_Vbuf[2 * P_INT * H_DIM];
__device__ int    d_gemmdone[NMT_MAX];
__device__ int    d_pwdone[NMT_MAX];
__device__ int    d_pwchain[P_INT];            // chain-feeding pw blocks done
__device__ int    d_crflag[P_INT];             // chainrow generation
__device__ int    d_vflag[P_INT];
__device__ int    d_qhead;

// ---------------- helpers ----------------
__device__ __forceinline__ uint32_t smem_u32(const void* p) {
    uint32_t a;
    asm("{ .reg .u64 t; cvta.to.shared.u64 t, %1; cvt.u32.u64 %0, t; }" : "=r"(a) : "l"(p));
    return a;
}
__device__ __forceinline__ void cpasync16(uint32_t dst, const void* src) {
    asm volatile("cp.async.cg.shared.global [%0], [%1], 16;"
                 :: "r"(dst), "l"(__cvta_generic_to_global(src)) : "memory");
}
__device__ __forceinline__ void ldm4(uint32_t* r, uint32_t addr) {
    asm volatile("ldmatrix.sync.aligned.m8n8.x4.shared.b16 {%0,%1,%2,%3}, [%4];"
                 : "=r"(r[0]), "=r"(r[1]), "=r"(r[2]), "=r"(r[3]) : "r"(addr));
}
__device__ __forceinline__ void mma16816(float* d, const uint32_t* a, uint32_t b0, uint32_t b1) {
    asm volatile(
        "mma.sync.aligned.m16n8k16.row.col.f32.f16.f16.f32 "
        "{%0,%1,%2,%3}, {%4,%5,%6,%7}, {%8,%9}, {%0,%1,%2,%3};"
        : "+f"(d[0]), "+f"(d[1]), "+f"(d[2]), "+f"(d[3])
        : "r"(a[0]), "r"(a[1]), "r"(a[2]), "r"(a[3]), "r"(b0), "r"(b1));
}
__device__ __forceinline__ int ld_acq(const int* p) {
    int v;
    asm volatile("ld.acquire.gpu.s32 %0, [%1];" : "=r"(v) : "l"(p) : "memory");
    return v;
}
__device__ __forceinline__ void spin_hot(const int* p, int tgt) {
    while (ld_acq(p) < tgt) { }
}
__device__ __forceinline__ void spin_bk(const int* p, int tgt) {
    if (ld_acq(p) >= tgt) return;
    while (ld_acq(p) < tgt) __nanosleep(64);
}
__device__ __forceinline__ void done_release(int* p) {
    asm volatile("red.release.gpu.global.add.s32 [%0], %1;"
                 :: "l"(__cvta_generic_to_global(p)), "r"(1) : "memory");
}
__device__ __forceinline__ void st_release(int* p, int v) {
    asm volatile("st.release.gpu.global.s32 [%0], %1;"
                 :: "l"(__cvta_generic_to_global(p)), "r"(v) : "memory");
}
__device__ __forceinline__ float tanh_fast(float x) {
    float y;
    asm("tanh.approx.f32 %0, %1;" : "=f"(y) : "f"(x));
    return y;
}

// ---------------- pack / convert / init ----------------
__global__ void pack_kernel(const float* __restrict__ Wf, const float* __restrict__ bf,
                            const float* __restrict__ Wi, const float* __restrict__ bi,
                            const float* __restrict__ Wo, const float* __restrict__ bo,
                            const float* __restrict__ Wg, const float* __restrict__ bg) {
    int idx = blockIdx.x * blockDim.x + threadIdx.x;
    if (idx < NG * KTOT) {
        int n = idx / KTOT;
        int k = idx % KTOT;
        int g = n >> 9, h = n & 511;
        const float* W = (g == 0) ? Wf : (g == 1) ? Wi : (g == 2) ? Wo : Wg;
        d_Wh[idx] = __float2half(W[k * H_DIM + h]);
    }
    if (idx < NG) {
        int g = idx / H_DIM, h = idx % H_DIM;
        const float* bb = (g == 0) ? bf : (g == 1) ? bi : (g == 2) ? bo : bg;
        d_Bcat[idx] = bb[h];
    }
}

__global__ void convx_kernel(const float* __restrict__ x) {
    int i = blockIdx.x * blockDim.x + threadIdx.x;
    d_Xh[i] = __float2half(x[i]);
}

__global__ void init_kernel() {
    int i = blockIdx.x * blockDim.x + threadIdx.x;
    if (i < P_INT * B_DIM * H_DIM) d_Hh[i] = __float2half(0.0f);
    if (i < NMT_MAX) { d_gemmdone[i] = 0; d_pwdone[i] = 0; }
    if (i < P_INT) { d_vflag[i] = 0; d_crflag[i] = 0; d_pwchain[i] = 0; }
    if (i == 0) d_qhead = 0;
}

// ---------------- stage loader ----------------
__device__ __forceinline__ void load_stage(uint32_t sa, uint32_t sbB, int tid, int ch,
                                           const __half* Xb, const __half* Hb, const __half* Wb) {
    const int k0 = ch * BK;
    const __half* asrc;
    int astride;
    if (k0 < F_DIM) { asrc = Xb + k0;           astride = F_DIM; }
    else            { asrc = Hb + (k0 - F_DIM); astride = H_DIM; }
    #pragma unroll
    for (int i = 0; i < 4; i++) {
        int cell = tid + i * 256;
        int r = cell >> 3, c = cell & 7;
        cpasync16(sa + r * 128 + ((c ^ (r & 7)) * 16),
                  asrc + (size_t)r * astride + c * 8);
    }
    #pragma unroll
    for (int i = 0; i < 4; i++) {
        int cell = tid + i * 256;
        int r = cell >> 3, c = cell & 7;
        cpasync16(sbB + r * 128 + ((c ^ (r & 7)) * 16),
                  Wb + (size_t)r * KTOT + k0 + c * 8);
    }
}

// ---------------- warp softmax over 512 values (16 per lane) ----------------
__device__ __forceinline__ void softmax16(float* s) {
    float mx = -1e30f;
    #pragma unroll
    for (int q = 0; q < 16; q++) mx = fmaxf(mx, s[q]);
    #pragma unroll
    for (int o = 16; o > 0; o >>= 1) mx = fmaxf(mx, __shfl_xor_sync(0xffffffffu, mx, o));
    float sum = 0.0f;
    #pragma unroll
    for (int q = 0; q < 16; q++) { s[q] = __expf(s[q] - mx); sum += s[q]; }
    #pragma unroll
    for (int o = 16; o > 0; o >>= 1) sum += __shfl_xor_sync(0xffffffffu, sum, o);
    const float inv = 1.0f / sum;
    #pragma unroll
    for (int q = 0; q < 16; q++) s[q] *= inv;
}
// element q of lane l <-> column (q>>1)*64 + l*2 + (q&1)
__device__ __forceinline__ void load_gate16(const __half2* base, int l, float* s) {
    #pragma unroll
    for (int q2 = 0; q2 < 8; q2++) {
        float2 v = __half22float2(base[q2 * 32 + l]);
        s[2 * q2] = v.x;
        s[2 * q2 + 1] = v.y;
    }
}

// ---------------- persistent fused kernel ----------------
__global__ void __launch_bounds__(256, 2) persist(float* __restrict__ out) {
    extern __shared__ char smem[];
    const int G = gridDim.x;
    const int tid = threadIdx.x;

    if ((int)blockIdx.x == G - 1) {
        // ===== chain CTA: one warp, register-resident v across ALL waves =====
        if (tid >= 32) return;
        const int l = tid;
        float v[16];
        #pragma unroll
        for (int q = 0; q < 16; q++) v[q] = 0.0f;

        for (int w = 0; w < NW; w++) {
            const int ns = (T_LEN - w * P_INT < P_INT) ? (T_LEN - w * P_INT) : P_INT;
            float* Vb = d_Vbuf + (w & 1) * P_INT * H_DIM;
            const float* SCb = d_Schain + (size_t)(w & 1) * (P_INT * NG);
            for (int j = 0; j < ns; j++) {
                // Vbuf bank safety: pw consumers of wave w-2 must be done
                if (w >= 2 && l < 4) spin_hot(&d_pwdone[4 * j + l], 16 * (w - 1));
                __syncwarp();
                #pragma unroll
                for (int q2 = 0; q2 < 8; q2++)
                    *(float2*)(Vb + j * H_DIM + q2 * 64 + l * 2) =
                        make_float2(v[2 * q2], v[2 * q2 + 1]);
                __threadfence();
                __syncwarp();
                // chainrow(w,j) must be done BEFORE vflag releases pw(w,j),
                // because pw(w,j) overwrites the Hh row chainrow reads.
                if (l == 0) spin_hot(&d_crflag[j], w + 1);
                __syncwarp();
                if (l == 0) st_release(&d_vflag[j], w + 1);

                const float* SC = SCb + (size_t)j * NG;
                float sf[16], si[16], sg[16];
                #pragma unroll
                for (int q2 = 0; q2 < 8; q2++) {
                    float2 a = *(const float2*)(SC + q2 * 64 + l * 2);
                    sf[2 * q2] = a.x; sf[2 * q2 + 1] = a.y;
                    float2 b = *(const float2*)(SC + 512 + q2 * 64 + l * 2);
                    si[2 * q2] = b.x; si[2 * q2 + 1] = b.y;
                    float2 c = *(const float2*)(SC + 1536 + q2 * 64 + l * 2);
                    sg[2 * q2] = c.x; sg[2 * q2 + 1] = c.y;
                }
                softmax16(sf);
                softmax16(si);
                #pragma unroll
                for (int q = 0; q < 16; q++)
                    v[q] = tanh_fast(sf[q] * v[q] + si[q] * tanh_fast(sg[q]));
            }
        }
        return;
    }

    // ===== worker CTA: global task queue =====
    __shared__ int s_task;
    const uint32_t sb = smem_u32(smem);
    const int wid = tid >> 5;
    const int l   = tid & 31;
    const int wm = (wid >> 2) * 64;
    const int wn = (wid & 3) * 32;
    const int lrow = l & 15;
    const int lk   = l >> 4;

    uint32_t sA[STG], sBs[STG];
    #pragma unroll
    for (int s = 0; s < STG; s++) {
        sA[s]  = sb + s * (A_SZ + B_SZ);
        sBs[s] = sA[s] + A_SZ;
    }

    while (true) {
        __syncthreads();
        if (tid == 0) s_task = atomicAdd(&d_qhead, 1);
        __syncthreads();
        const int task = s_task;
        if (task >= TOTAL_TASKS) break;

        int w, rm;
        int kind;           // 0 = chainrow, 1 = gemm, 2 = pw
        int crj = 0, mtile = 0, n0 = 0, pwb = 0;
        if (task < FULL_TASKS) {
            w = task / NTASK_WAVE;
            rm = task % NTASK_WAVE;
            if (rm < 12)            { kind = 0; crj = rm; }
            else if (rm < 780)      { kind = 1; int rr = rm - 12; mtile = rr >> 4; n0 = (rr & 15) * BN; }
            else                    { kind = 2; pwb = rm - 780; }
        } else {
            w = 21;
            rm = task - FULL_TASKS;
            if (rm < LAST_CR)              { kind = 0; crj = rm; }
            else if (rm < LAST_CR + LAST_G){ kind = 1; int rr = rm - LAST_CR; mtile = 12 + (rr >> 4); n0 = (rr & 15) * BN; }
            else                           { kind = 2; pwb = 192 + (rm - LAST_CR - LAST_G); }
        }
        const int t0 = w * P_INT;
        __half* Sb = d_Sbuf + (size_t)(w & 1) * WAVE_S;

        if (kind == 0) {
            // ---- chainrow: one S row (batch r of step j), 2048 gates, fp32 ----
            const int j = crj;
            const int r = (j + 1) % P_INT;
            if (tid == 0) spin_bk(&d_pwchain[j], w);
            __syncthreads();
            __half* Arow = (__half*)smem;
            if (tid < 32) {
                ((uint4*)Arow)[tid] =
                    ((const uint4*)(d_Xh + ((size_t)(t0 + j) * B_DIM + r) * F_DIM))[tid];
            } else if (tid < 96) {
                ((uint4*)(Arow + F_DIM))[tid - 32] =
                    ((const uint4*)(d_Hh + (size_t)(j * B_DIM + r) * H_DIM))[tid - 32];
            }
            __syncthreads();
            // lane l covers k in 3 groups of 8 halfs: [l*8, l*8+8)+g*256
            float af[24];
            {
                const __half2* A2 = (const __half2*)Arow;
                #pragma unroll
                for (int g = 0; g < 3; g++)
                    #pragma unroll
                    for (int p = 0; p < 4; p++) {
                        float2 t = __half22float2(A2[(l + g * 32) * 4 + p]);
                        af[g * 8 + p * 2]     = t.x;
                        af[g * 8 + p * 2 + 1] = t.y;
                    }
            }
            float* outrow = d_Schain + (size_t)(w & 1) * (P_INT * NG) + (size_t)j * NG;
            #pragma unroll 2
            for (int nn = 0; nn < 256; nn++) {
                const int n = wid * 256 + nn;
                const uint4* wr = (const uint4*)(d_Wh + (size_t)n * KTOT);
                float acc = 0.0f;
                #pragma unroll
                for (int g = 0; g < 3; g++) {
                    uint4 wv = wr[l + g * 32];
                    const __half2* w2 = (const __half2*)&wv;
                    #pragma unroll
                    for (int p = 0; p < 4; p++) {
                        float2 t = __half22float2(w2[p]);
                        acc += af[g * 8 + p * 2] * t.x + af[g * 8 + p * 2 + 1] * t.y;
                    }
                }
                #pragma unroll
                for (int o = 16; o > 0; o >>= 1)
                    acc += __shfl_xor_sync(0xffffffffu, acc, o);
                if (l == 0) outrow[n] = acc + d_Bcat[n];
            }
            __syncthreads();
            if (tid == 0) st_release(&d_crflag[j], w + 1);
        } else if (kind == 1) {
            // ---- GEMM tile ----
            const int m0 = mtile * BM;
            const __half* Xb = d_Xh + ((size_t)t0 * B_DIM + m0) * F_DIM;
            const __half* Hb = d_Hh + (size_t)m0 * H_DIM;
            const __half* Wb = d_Wh + (size_t)n0 * KTOT;

            float acc[4][4][4];
            #pragma unroll
            for (int i = 0; i < 4; i++)
                #pragma unroll
                for (int j = 0; j < 4; j++)
                    #pragma unroll
                    for (int q = 0; q < 4; q++) acc[i][j][q] = 0.0f;

            #pragma unroll
            for (int c = 0; c < STG - 1; c++) {
                load_stage(sA[c], sBs[c], tid, c, Xb, Hb, Wb);
                asm volatile("cp.async.commit_group;" ::: "memory");
            }

            for (int ch = 0; ch < NCH; ch++) {
                asm volatile("cp.async.wait_group 1;" ::: "memory");
                __syncthreads();
                const int cl = ch + STG - 1;
                if (cl == 4)
                    spin_bk(&d_pwdone[mtile], 16 * w);
                if (cl < NCH)
                    load_stage(sA[cl % STG], sBs[cl % STG], tid, cl, Xb, Hb, Wb);
                asm volatile("cp.async.commit_group;" ::: "memory");

                const int s = ch % STG;
                #pragma unroll
                for (int kk = 0; kk < BK / 16; kk++) {
                    uint32_t af[4][4], bfr[2][4];
                    #pragma unroll
                    for (int mi = 0; mi < 4; mi++) {
                        int rr = wm + mi * 16 + lrow;
                        int cc = kk * 2 + lk;
                        ldm4(af[mi], sA[s] + rr * 128 + ((cc ^ (rr & 7)) * 16));
                    }
                    #pragma unroll
                    for (int bj = 0; bj < 2; bj++) {
                        int rr = wn + bj * 16 + lrow;
                        int cc = kk * 2 + lk;
                        ldm4(bfr[bj], sBs[s] + rr * 128 + ((cc ^ (rr & 7)) * 16));
                    }
                    #pragma unroll
                    for (int mi = 0; mi < 4; mi++)
                        #pragma unroll
                        for (int nj = 0; nj < 4; nj++)
                            mma16816(acc[mi][nj], af[mi],
                                     bfr[nj >> 1][nj & 1], bfr[nj >> 1][(nj & 1) + 2]);
                }
            }

            __half2* S2 = (__half2*)Sb;
            #pragma unroll
            for (int mi = 0; mi < 4; mi++) {
                #pragma unroll
                for (int nj = 0; nj < 4; nj++) {
                    int m = m0 + wm + mi * 16 + (l >> 2);
                    int n = n0 + wn + nj * 8 + (l & 3) * 2;
                    float b0 = d_Bcat[n], b1 = d_Bcat[n + 1];
                    S2[((size_t)m * NG + n) >> 1] =
                        __floats2half2_rn(acc[mi][nj][0] + b0, acc[mi][nj][1] + b1);
                    S2[((size_t)(m + 8) * NG + n) >> 1] =
                        __floats2half2_rn(acc[mi][nj][2] + b0, acc[mi][nj][3] + b1);
                }
            }
            __syncthreads();
            if (tid == 0) done_release(&d_gemmdone[mtile]);
        } else {
            // ---- pointwise block: 8 rows, warp per row ----
            const int b = pwb;
            const int mt = b >> 4;
            const int j  = b >> 6;
            if (tid == 0) spin_bk(&d_gemmdone[mt], 16 * (w + 1));
            __syncthreads();

            const int m = b * 8 + wid;
            const float* Vb = d_Vbuf + (w & 1) * P_INT * H_DIM;
            const __half2* S = (const __half2*)Sb + (((size_t)m * NG) >> 1);
            float sf[16], si[16], so[16], sg[16];
            load_gate16(S, l, sf);
            load_gate16(S + (H_DIM >> 1), l, si);
            load_gate16(S + ((2 * H_DIM) >> 1), l, so);
            load_gate16(S + ((3 * H_DIM) >> 1), l, sg);
            softmax16(sf);
            softmax16(si);
            softmax16(so);

            if (tid == 0) spin_bk(&d_vflag[j], w + 1);
            __syncthreads();

            __half2* Hh2 = (__half2*)d_Hh;
            const bool wout = (j == 3);
            #pragma unroll
            for (int q2 = 0; q2 < 8; q2++) {
                float2 vv = *(const float2*)(Vb + j * H_DIM + q2 * 64 + l * 2);
                float c0 = tanh_fast(sf[2 * q2] * vv.x + si[2 * q2] * tanh_fast(sg[2 * q2]));
                float c1 = tanh_fast(sf[2 * q2 + 1] * vv.y + si[2 * q2 + 1] * tanh_fast(sg[2 * q2 + 1]));
                float h0 = so[2 * q2] * c0;
                float h1 = so[2 * q2 + 1] * c1;
                Hh2[((size_t)m * H_DIM + q2 * 64 + l * 2) >> 1] = __floats2half2_rn(h0, h1);
                if (wout)
                    *(float2*)(out + (size_t)(m & 511) * H_DIM + q2 * 64 + l * 2) =
                        make_float2(h0, h1);
            }
            __syncthreads();
            if (tid == 0) {
                // chain-feeding block? (row j*512 + (j+1)%12 lives in block j*64 + (r>>3))
                const int rr = ((j + 1) % P_INT) >> 3;
                if ((b & 63) == rr) done_release(&d_pwchain[j]);
                done_release(&d_pwdone[mt]);
            }
        }
    }
}

// ---------------- launch ----------------
extern "C" void kernel_launch(void* const* d_in, const int* in_sizes, int n_in,
                              void* d_out, int out_size) {
    const float* x  = (const float*)d_in[0];
    const float* Wf = (const float*)d_in[1];
    const float* bf = (const float*)d_in[2];
    const float* Wi = (const float*)d_in[3];
    const float* bi = (const float*)d_in[4];
    const float* Wo = (const float*)d_in[5];
    const float* bo = (const float*)d_in[6];
    const float* Wg = (const float*)d_in[7];
    const float* bg = (const float*)d_in[8];
    float* out = (float*)d_out;

    cudaFuncSetAttribute(persist, cudaFuncAttributeMaxDynamicSharedMemorySize, SMEM_BYTES);

    int sms = 0, occ = 0;
    cudaDeviceGetAttribute(&sms, cudaDevAttrMultiProcessorCount, 0);
    cudaOccupancyMaxActiveBlocksPerMultiprocessor(&occ, persist, 256, SMEM_BYTES);
    if (occ < 1) occ = 1;
    int G = occ * sms;
    if (G > 297) G = 297;
    if (G < 2) G = 2;

    {
        int n = NG * KTOT;
        pack_kernel<<<(n + 255) / 256, 256>>>(Wf, bf, Wi, bi, Wo, bo, Wg, bg);
    }
    {
        int n = T_LEN * B_DIM * F_DIM;
        convx_kernel<<<n / 256, 256>>>(x);
    }
    {
        int n = P_INT * B_DIM * H_DIM;
        init_kernel<<<(n + 255) / 256, 256>>>();
    }

    persist<<<G, 256, SMEM_BYTES>>>(out);
}

// round 11
// speedup vs baseline: 1.6047x; 1.6047x over previous
#include <cuda_runtime.h>
#include <cuda_fp16.h>
#include <cstdint>
#include <math.h>

#define T_LEN 256
#define B_DIM 512
#define F_DIM 256
#define H_DIM 512
#define P_INT 12
#define KTOT  768
#define NG    2048
#define NW    22

// ---------------- GEMM tiling ----------------
#define BM 128
#define BN 128
#define BK 64
#define STG 3

#define A_SZ (BM * BK * 2)
#define B_SZ (BN * BK * 2)
#define SMEM_BYTES (STG * (A_SZ + B_SZ))  // 96 KB

#define WAVE_ROWS (P_INT * B_DIM)
#define WAVE_S ((size_t)WAVE_ROWS * NG)
#define NMT_MAX 48

// queue segment boundaries (see decode)
#define T0 768        // xgemm(0)
#define T1 2304       // region0: xgemm(1) 768 + hgemm(0) 768
#define T2 46080      // regions w=1..19: 19 x [xgemm(w+1) 768 | pw(w-1) 768 | hgemm(w) 768]
#define T3 47728      // region20: xgemm(21) 112 | pw(19) 768 | hgemm(20) 768
#define T4 48608      // region21: pw(20) 768 | hgemm(21) 112
#define TOTAL_TASKS 48672   // T4 + pw(21) 64  (INCLUSIVE of the final 64)

__device__ __constant__ int c_lastmt[7] = {0, 4, 8, 12, 13, 14, 15};

// ---------------- static device scratch ----------------
__device__ __half d_Wh[NG * KTOT];
__device__ float  d_Bcat[NG];
__device__ __half d_Xh[T_LEN * B_DIM * F_DIM];
__device__ __half d_Hh[P_INT * B_DIM * H_DIM];
__device__ __half d_Sbuf[2 * WAVE_S];          // full preactivations, dbl-buffered
__device__ __half d_Sx[2 * WAVE_S];            // x-part (+bias), dbl-buffered
__device__ float  d_Vbuf[2 * P_INT * H_DIM];
__device__ int    d_gemmdone[NMT_MAX];         // hgemm tiles done per mtile
__device__ int    d_xdone[NMT_MAX];            // xgemm tiles done per mtile
__device__ int    d_pwdone[NMT_MAX];
__device__ int    d_vflag[P_INT];
__device__ int    d_qhead;

// ---------------- helpers ----------------
__device__ __forceinline__ uint32_t smem_u32(const void* p) {
    uint32_t a;
    asm("{ .reg .u64 t; cvta.to.shared.u64 t, %1; cvt.u32.u64 %0, t; }" : "=r"(a) : "l"(p));
    return a;
}
__device__ __forceinline__ void cpasync16(uint32_t dst, const void* src) {
    asm volatile("cp.async.cg.shared.global [%0], [%1], 16;"
                 :: "r"(dst), "l"(__cvta_generic_to_global(src)) : "memory");
}
__device__ __forceinline__ void ldm4(uint32_t* r, uint32_t addr) {
    asm volatile("ldmatrix.sync.aligned.m8n8.x4.shared.b16 {%0,%1,%2,%3}, [%4];"
                 : "=r"(r[0]), "=r"(r[1]), "=r"(r[2]), "=r"(r[3]) : "r"(addr));
}
__device__ __forceinline__ void mma16816(float* d, const uint32_t* a, uint32_t b0, uint32_t b1) {
    asm volatile(
        "mma.sync.aligned.m16n8k16.row.col.f32.f16.f16.f32 "
        "{%0,%1,%2,%3}, {%4,%5,%6,%7}, {%8,%9}, {%0,%1,%2,%3};"
        : "+f"(d[0]), "+f"(d[1]), "+f"(d[2]), "+f"(d[3])
        : "r"(a[0]), "r"(a[1]), "r"(a[2]), "r"(a[3]), "r"(b0), "r"(b1));
}
__device__ __forceinline__ int ld_acq(const int* p) {
    int v;
    asm volatile("ld.acquire.gpu.s32 %0, [%1];" : "=r"(v) : "l"(p) : "memory");
    return v;
}
__device__ __forceinline__ void spin_hot(const int* p, int tgt) {
    while (ld_acq(p) < tgt) { }
}
__device__ __forceinline__ void spin_bk(const int* p, int tgt) {
    if (ld_acq(p) >= tgt) return;
    while (ld_acq(p) < tgt) __nanosleep(64);
}
__device__ __forceinline__ void done_release(int* p) {
    asm volatile("red.release.gpu.global.add.s32 [%0], %1;"
                 :: "l"(__cvta_generic_to_global(p)), "r"(1) : "memory");
}
__device__ __forceinline__ float tanh_fast(float x) {
    float y;
    asm("tanh.approx.f32 %0, %1;" : "=f"(y) : "f"(x));
    return y;
}

// ---------------- pack / convert / init ----------------
__global__ void pack_kernel(const float* __restrict__ Wf, const float* __restrict__ bf,
                            const float* __restrict__ Wi, const float* __restrict__ bi,
                            const float* __restrict__ Wo, const float* __restrict__ bo,
                            const float* __restrict__ Wg, const float* __restrict__ bg) {
    int idx = blockIdx.x * blockDim.x + threadIdx.x;
    if (idx < NG * KTOT) {
        int n = idx / KTOT;
        int k = idx % KTOT;
        int g = n >> 9, h = n & 511;
        const float* W = (g == 0) ? Wf : (g == 1) ? Wi : (g == 2) ? Wo : Wg;
        d_Wh[idx] = __float2half(W[k * H_DIM + h]);
    }
    if (idx < NG) {
        int g = idx / H_DIM, h = idx % H_DIM;
        const float* bb = (g == 0) ? bf : (g == 1) ? bi : (g == 2) ? bo : bg;
        d_Bcat[idx] = bb[h];
    }
}

__global__ void convx_kernel(const float* __restrict__ x) {
    int i = blockIdx.x * blockDim.x + threadIdx.x;
    d_Xh[i] = __float2half(x[i]);
}

__global__ void init_kernel() {
    int i = blockIdx.x * blockDim.x + threadIdx.x;
    if (i < P_INT * B_DIM * H_DIM) d_Hh[i] = __float2half(0.0f);
    if (i < NMT_MAX) { d_gemmdone[i] = 0; d_pwdone[i] = 0; d_xdone[i] = 0; }
    if (i < P_INT) d_vflag[i] = 0;
    if (i == 0) d_qhead = 0;
}

// ---------------- stage loader (generic A source / K offset) ----------------
__device__ __forceinline__ void load_stage(uint32_t sa, uint32_t sbB, int tid, int k0,
                                           const __half* Asrc, int astride, const __half* Wb) {
    #pragma unroll
    for (int i = 0; i < 4; i++) {
        int cell = tid + i * 256;
        int r = cell >> 3, c = cell & 7;
        cpasync16(sa + r * 128 + ((c ^ (r & 7)) * 16),
                  Asrc + (size_t)r * astride + k0 + c * 8);
    }
    #pragma unroll
    for (int i = 0; i < 4; i++) {
        int cell = tid + i * 256;
        int r = cell >> 3, c = cell & 7;
        cpasync16(sbB + r * 128 + ((c ^ (r & 7)) * 16),
                  Wb + (size_t)r * KTOT + k0 + c * 8);
    }
}

// ---------------- warp softmax over 512 values (16 per lane) ----------------
__device__ __forceinline__ void softmax16(float* s) {
    float mx = -1e30f;
    #pragma unroll
    for (int q = 0; q < 16; q++) mx = fmaxf(mx, s[q]);
    #pragma unroll
    for (int o = 16; o > 0; o >>= 1) mx = fmaxf(mx, __shfl_xor_sync(0xffffffffu, mx, o));
    float sum = 0.0f;
    #pragma unroll
    for (int q = 0; q < 16; q++) { s[q] = __expf(s[q] - mx); sum += s[q]; }
    #pragma unroll
    for (int o = 16; o > 0; o >>= 1) sum += __shfl_xor_sync(0xffffffffu, sum, o);
    const float inv = 1.0f / sum;
    #pragma unroll
    for (int q = 0; q < 16; q++) s[q] *= inv;
}
// element q of lane l <-> column (q>>1)*64 + l*2 + (q&1)
__device__ __forceinline__ void load_gate16(const __half2* base, int l, float* s) {
    #pragma unroll
    for (int q2 = 0; q2 < 8; q2++) {
        float2 v = __half22float2(base[q2 * 32 + l]);
        s[2 * q2] = v.x;
        s[2 * q2 + 1] = v.y;
    }
}

// ---------------- persistent fused kernel ----------------
__global__ void __launch_bounds__(256, 2) persist(float* __restrict__ out) {
    extern __shared__ char smem[];
    const int G = gridDim.x;
    const int tid = threadIdx.x;

    if ((int)blockIdx.x == G - 1) {
        // ===== chain CTA: one warp, register-resident v across ALL waves =====
        if (tid >= 32) return;
        const int l = tid;
        float v[16];
        #pragma unroll
        for (int q = 0; q < 16; q++) v[q] = 0.0f;

        for (int w = 0; w < NW; w++) {
            const int t0 = w * P_INT;
            const int ns = (T_LEN - t0 < P_INT) ? (T_LEN - t0) : P_INT;
            const __half2* Sb2 = (const __half2*)(d_Sbuf + (size_t)(w & 1) * WAVE_S);
            float* Vb = d_Vbuf + (w & 1) * P_INT * H_DIM;
            for (int j = 0; j < ns; j++) {
                if (w >= 2 && l < 4) spin_hot(&d_pwdone[4 * j + l], 16 * (w - 1));
                __syncwarp();
                #pragma unroll
                for (int q2 = 0; q2 < 8; q2++)
                    *(float2*)(Vb + j * H_DIM + q2 * 64 + l * 2) =
                        make_float2(v[2 * q2], v[2 * q2 + 1]);
                __threadfence();
                __syncwarp();
                if (l == 0)
                    asm volatile("st.release.gpu.s32 [%0], %1;"
                                 :: "l"(d_vflag + j), "r"(w + 1) : "memory");
                spin_hot(&d_gemmdone[4 * j], 16 * (w + 1));
                const int r = (t0 + j + 1) % P_INT;
                const __half2* S = Sb2 + (((size_t)(j * B_DIM + r) * NG) >> 1);
                float sf[16], si[16], sg[16];
                load_gate16(S, l, sf);
                load_gate16(S + (H_DIM >> 1), l, si);
                load_gate16(S + ((3 * H_DIM) >> 1), l, sg);
                softmax16(sf);
                softmax16(si);
                #pragma unroll
                for (int q = 0; q < 16; q++)
                    v[q] = tanh_fast(sf[q] * v[q] + si[q] * tanh_fast(sg[q]));
            }
        }
        return;
    }

    // ===== worker CTA: global task queue =====
    __shared__ int s_task;
    const uint32_t sb = smem_u32(smem);
    const int wid = tid >> 5;
    const int l   = tid & 31;
    const int wm = (wid >> 2) * 64;
    const int wn = (wid & 3) * 32;
    const int lrow = l & 15;
    const int lk   = l >> 4;

    uint32_t sA[STG], sBs[STG];
    #pragma unroll
    for (int s = 0; s < STG; s++) {
        sA[s]  = sb + s * (A_SZ + B_SZ);
        sBs[s] = sA[s] + A_SZ;
    }

    while (true) {
        __syncthreads();
        if (tid == 0) s_task = atomicAdd(&d_qhead, 1);
        __syncthreads();
        const int task = s_task;
        if (task >= TOTAL_TASKS) break;

        // ---- decode: kind 0 = xgemm(wv), 1 = hgemm(wv), 2 = pw(pww) ----
        int kind, wv = 0, mt = 0, n0 = 0, pwb = 0, pww = 0;
        if (task < T0) {
            kind = 0; wv = 0; mt = task >> 4; n0 = (task & 15) * BN;
        } else if (task < T1) {
            int r = task - T0;
            if (r < 768) { kind = 0; wv = 1; mt = r >> 4; n0 = (r & 15) * BN; }
            else { int rr = r - 768; kind = 1; wv = 0;
                   mt = ((rr % 192) >> 4) * 4 + rr / 192; n0 = (rr & 15) * BN; }
        } else if (task < T2) {
            int q = task - T1;
            int w = 1 + q / 2304, r = q % 2304;
            if (r < 768)       { kind = 0; wv = w + 1; mt = r >> 4; n0 = (r & 15) * BN; }
            else if (r < 1536) { kind = 2; pww = w - 1; pwb = r - 768; }
            else { int rr = r - 1536; kind = 1; wv = w;
                   mt = ((rr % 192) >> 4) * 4 + rr / 192; n0 = (rr & 15) * BN; }
        } else if (task < T3) {
            int r = task - T2;
            if (r < 112)      { kind = 0; wv = 21; mt = c_lastmt[r >> 4]; n0 = (r & 15) * BN; }
            else if (r < 880) { kind = 2; pww = 19; pwb = r - 112; }
            else { int rr = r - 880; kind = 1; wv = 20;
                   mt = ((rr % 192) >> 4) * 4 + rr / 192; n0 = (rr & 15) * BN; }
        } else if (task < T4) {
            int r = task - T3;
            if (r < 768) { kind = 2; pww = 20; pwb = r; }
            else { int rr = r - 768; kind = 1; wv = 21; mt = c_lastmt[rr >> 4]; n0 = (rr & 15) * BN; }
        } else {
            kind = 2; pww = 21; pwb = 192 + (task - T4);   // 64 tasks, j == 3 only
        }

        if (kind <= 1) {
            // ---- GEMM tile (xgemm: K=256 from X; hgemm: K=512 from Hh, + Sx) ----
            const bool isx = (kind == 0);
            const int m0 = mt * BM;
            const int nch = isx ? 4 : 8;
            const __half* Asrc = isx ? (d_Xh + ((size_t)wv * P_INT * B_DIM + m0) * F_DIM)
                                     : (d_Hh + (size_t)m0 * H_DIM);
            const int astride = isx ? F_DIM : H_DIM;
            const __half* Wb = d_Wh + (size_t)n0 * KTOT + (isx ? 0 : F_DIM);

            if (isx) {
                if (wv >= 2) spin_bk(&d_gemmdone[mt], 16 * (wv - 1));   // Sx bank reuse
            } else {
                if (wv >= 1) spin_bk(&d_pwdone[mt], 16 * wv);           // Hh ready
            }

            float acc[4][4][4];
            #pragma unroll
            for (int i = 0; i < 4; i++)
                #pragma unroll
                for (int j = 0; j < 4; j++)
                    #pragma unroll
                    for (int q = 0; q < 4; q++) acc[i][j][q] = 0.0f;

            #pragma unroll
            for (int c = 0; c < STG - 1; c++) {
                load_stage(sA[c], sBs[c], tid, c * BK, Asrc, astride, Wb);
                asm volatile("cp.async.commit_group;" ::: "memory");
            }

            for (int ch = 0; ch < nch; ch++) {
                asm volatile("cp.async.wait_group 1;" ::: "memory");
                __syncthreads();
                const int cl = ch + STG - 1;
                if (cl < nch)
                    load_stage(sA[cl % STG], sBs[cl % STG], tid, cl * BK, Asrc, astride, Wb);
                asm volatile("cp.async.commit_group;" ::: "memory");

                const int s = ch % STG;
                #pragma unroll
                for (int kk = 0; kk < BK / 16; kk++) {
                    uint32_t af[4][4], bfr[2][4];
                    #pragma unroll
                    for (int mi = 0; mi < 4; mi++) {
                        int rr = wm + mi * 16 + lrow;
                        int cc = kk * 2 + lk;
                        ldm4(af[mi], sA[s] + rr * 128 + ((cc ^ (rr & 7)) * 16));
                    }
                    #pragma unroll
                    for (int bj = 0; bj < 2; bj++) {
                        int rr = wn + bj * 16 + lrow;
                        int cc = kk * 2 + lk;
                        ldm4(bfr[bj], sBs[s] + rr * 128 + ((cc ^ (rr & 7)) * 16));
                    }
                    #pragma unroll
                    for (int mi = 0; mi < 4; mi++)
                        #pragma unroll
                        for (int nj = 0; nj < 4; nj++)
                            mma16816(acc[mi][nj], af[mi],
                                     bfr[nj >> 1][nj & 1], bfr[nj >> 1][(nj & 1) + 2]);
                }
            }

            if (isx) {
                // epilogue: + bias -> Sx bank wv&1
                __half2* X2 = (__half2*)(d_Sx + (size_t)(wv & 1) * WAVE_S);
                #pragma unroll
                for (int mi = 0; mi < 4; mi++) {
                    #pragma unroll
                    for (int nj = 0; nj < 4; nj++) {
                        int m = m0 + wm + mi * 16 + (l >> 2);
                        int n = n0 + wn + nj * 8 + (l & 3) * 2;
                        float b0 = d_Bcat[n], b1 = d_Bcat[n + 1];
                        X2[((size_t)m * NG + n) >> 1] =
                            __floats2half2_rn(acc[mi][nj][0] + b0, acc[mi][nj][1] + b1);
                        X2[((size_t)(m + 8) * NG + n) >> 1] =
                            __floats2half2_rn(acc[mi][nj][2] + b0, acc[mi][nj][3] + b1);
                    }
                }
                __syncthreads();
                if (tid == 0) done_release(&d_xdone[mt]);
            } else {
                // epilogue: + Sx -> Sbuf bank wv&1
                spin_bk(&d_xdone[mt], 16 * (wv + 1));    // Sx tile ready (pre-satisfied)
                const __half2* X2 = (const __half2*)(d_Sx + (size_t)(wv & 1) * WAVE_S);
                __half2* S2 = (__half2*)(d_Sbuf + (size_t)(wv & 1) * WAVE_S);
                #pragma unroll
                for (int mi = 0; mi < 4; mi++) {
                    #pragma unroll
                    for (int nj = 0; nj < 4; nj++) {
                        int m = m0 + wm + mi * 16 + (l >> 2);
                        int n = n0 + wn + nj * 8 + (l & 3) * 2;
                        float2 x0 = __half22float2(X2[((size_t)m * NG + n) >> 1]);
                        float2 x1 = __half22float2(X2[((size_t)(m + 8) * NG + n) >> 1]);
                        S2[((size_t)m * NG + n) >> 1] =
                            __floats2half2_rn(acc[mi][nj][0] + x0.x, acc[mi][nj][1] + x0.y);
                        S2[((size_t)(m + 8) * NG + n) >> 1] =
                            __floats2half2_rn(acc[mi][nj][2] + x1.x, acc[mi][nj][3] + x1.y);
                    }
                }
                __syncthreads();
                if (tid == 0) done_release(&d_gemmdone[mt]);
            }
        } else {
            // ---- pointwise block: 8 rows, warp per row ----
            const int w = pww;
            const int b = pwb;
            const int mtb = b >> 4;
            const int j  = b >> 6;
            if (tid == 0) spin_bk(&d_gemmdone[mtb], 16 * (w + 1));
            __syncthreads();

            const int m = b * 8 + wid;
            const float* Vb = d_Vbuf + (w & 1) * P_INT * H_DIM;
            const __half2* S = (const __half2*)(d_Sbuf + (size_t)(w & 1) * WAVE_S)
                               + (((size_t)m * NG) >> 1);
            float sf[16], si[16], so[16], sg[16];
            load_gate16(S, l, sf);
            load_gate16(S + (H_DIM >> 1), l, si);
            load_gate16(S + ((2 * H_DIM) >> 1), l, so);
            load_gate16(S + ((3 * H_DIM) >> 1), l, sg);
            softmax16(sf);
            softmax16(si);
            softmax16(so);

            if (tid == 0) spin_bk(&d_vflag[j], w + 1);
            __syncthreads();

            __half2* Hh2 = (__half2*)d_Hh;
            const bool wout = (j == 3);
            #pragma unroll
            for (int q2 = 0; q2 < 8; q2++) {
                float2 vv = *(const float2*)(Vb + j * H_DIM + q2 * 64 + l * 2);
                float c0 = tanh_fast(sf[2 * q2] * vv.x + si[2 * q2] * tanh_fast(sg[2 * q2]));
                float c1 = tanh_fast(sf[2 * q2 + 1] * vv.y + si[2 * q2 + 1] * tanh_fast(sg[2 * q2 + 1]));
                float h0 = so[2 * q2] * c0;
                float h1 = so[2 * q2 + 1] * c1;
                Hh2[((size_t)m * H_DIM + q2 * 64 + l * 2) >> 1] = __floats2half2_rn(h0, h1);
                if (wout)
                    *(float2*)(out + (size_t)(m & 511) * H_DIM + q2 * 64 + l * 2) =
                        make_float2(h0, h1);
            }
            __syncthreads();
            if (tid == 0) done_release(&d_pwdone[mtb]);
        }
    }
}

// ---------------- launch ----------------
extern "C" void kernel_launch(void* const* d_in, const int* in_sizes, int n_in,
                              void* d_out, int out_size) {
    const float* x  = (const float*)d_in[0];
    const float* Wf = (const float*)d_in[1];
    const float* bf = (const float*)d_in[2];
    const float* Wi = (const float*)d_in[3];
    const float* bi = (const float*)d_in[4];
    const float* Wo = (const float*)d_in[5];
    const float* bo = (const float*)d_in[6];
    const float* Wg = (const float*)d_in[7];
    const float* bg = (const float*)d_in[8];
    float* out = (float*)d_out;

    cudaFuncSetAttribute(persist, cudaFuncAttributeMaxDynamicSharedMemorySize, SMEM_BYTES);

    int sms = 0, occ = 0;
    cudaDeviceGetAttribute(&sms, cudaDevAttrMultiProcessorCount, 0);
    cudaOccupancyMaxActiveBlocksPerMultiprocessor(&occ, persist, 256, SMEM_BYTES);
    if (occ < 1) occ = 1;
    int G = occ * sms;
    if (G > 297) G = 297;
    if (G < 2) G = 2;

    {
        int n = NG * KTOT;
        pack_kernel<<<(n + 255) / 256, 256>>>(Wf, bf, Wi, bi, Wo, bo, Wg, bg);
    }
    {
        int n = T_LEN * B_DIM * F_DIM;
        convx_kernel<<<n / 256, 256>>>(x);
    }
    {
        int n = P_INT * B_DIM * H_DIM;
        init_kernel<<<(n + 255) / 256, 256>>>();
    }

    persist<<<G, 256, SMEM_BYTES>>>(out);
}

// round 12
// speedup vs baseline: 1.8583x; 1.1581x over previous
#include <cuda_runtime.h>
#include <cuda_fp16.h>
#include <cstdint>
#include <math.h>

#define T_LEN 256
#define B_DIM 512
#define F_DIM 256
#define H_DIM 512
#define P_INT 12
#define KTOT  768
#define NG    2048
#define NW    22

// ---------------- GEMM tiling ----------------
#define BM 128
#define BN 128
#define BK 64
#define STG 3
#define NCH (KTOT / BK)

#define A_SZ (BM * BK * 2)
#define B_SZ (BN * BK * 2)
#define SMEM_BYTES (STG * (A_SZ + B_SZ))  // 96 KB

#define WAVE_ROWS (P_INT * B_DIM)
#define WAVE_S ((size_t)WAVE_ROWS * NG)
#define NMT_MAX 48

// queue: 512 conv tasks | 21 x [gemm 768 | pw 768] | gemm(21) 112 | pw(21) 64
#define NCONV 512
#define FULL_TASKS (21 * 1536)
#define LAST_GEMM 112
#define TOTAL_TASKS (NCONV + FULL_TASKS + LAST_GEMM + 64)

__device__ __constant__ int c_lastmt[7] = {0, 4, 8, 12, 13, 14, 15};
// n-tile visit order: f,i (0-7) then g (12-15) then o (8-11) — chain needs f,i,g only
__device__ __constant__ int c_ntord[16] = {0,1,2,3,4,5,6,7,12,13,14,15,8,9,10,11};

// ---------------- static device scratch ----------------
__device__ __half d_Wh[NG * KTOT];
__device__ float  d_Bcat[NG];
__device__ __half d_Xh[T_LEN * B_DIM * F_DIM];
__device__ __half d_Hh[P_INT * B_DIM * H_DIM];
__device__ __half d_Sbuf[2 * WAVE_S];
__device__ float  d_Vbuf[2 * P_INT * H_DIM];
__device__ int    d_gemmdone[NMT_MAX];
__device__ int    d_gchain[P_INT];     // chain-relevant (f,i,g) tiles of feeder mtiles
__device__ int    d_pwdone[NMT_MAX];
__device__ int    d_xcdone[NW];        // x-conversion tasks done per wave
__device__ int    d_vflag[P_INT];
__device__ int    d_qhead;

// ---------------- helpers ----------------
__device__ __forceinline__ uint32_t smem_u32(const void* p) {
    uint32_t a;
    asm("{ .reg .u64 t; cvta.to.shared.u64 t, %1; cvt.u32.u64 %0, t; }" : "=r"(a) : "l"(p));
    return a;
}
__device__ __forceinline__ void cpasync16(uint32_t dst, const void* src) {
    asm volatile("cp.async.cg.shared.global [%0], [%1], 16;"
                 :: "r"(dst), "l"(__cvta_generic_to_global(src)) : "memory");
}
__device__ __forceinline__ void ldm4(uint32_t* r, uint32_t addr) {
    asm volatile("ldmatrix.sync.aligned.m8n8.x4.shared.b16 {%0,%1,%2,%3}, [%4];"
                 : "=r"(r[0]), "=r"(r[1]), "=r"(r[2]), "=r"(r[3]) : "r"(addr));
}
__device__ __forceinline__ void mma16816(float* d, const uint32_t* a, uint32_t b0, uint32_t b1) {
    asm volatile(
        "mma.sync.aligned.m16n8k16.row.col.f32.f16.f16.f32 "
        "{%0,%1,%2,%3}, {%4,%5,%6,%7}, {%8,%9}, {%0,%1,%2,%3};"
        : "+f"(d[0]), "+f"(d[1]), "+f"(d[2]), "+f"(d[3])
        : "r"(a[0]), "r"(a[1]), "r"(a[2]), "r"(a[3]), "r"(b0), "r"(b1));
}
__device__ __forceinline__ int ld_acq(const int* p) {
    int v;
    asm volatile("ld.acquire.gpu.s32 %0, [%1];" : "=r"(v) : "l"(p) : "memory");
    return v;
}
__device__ __forceinline__ void spin_hot(const int* p, int tgt) {
    while (ld_acq(p) < tgt) { }
}
__device__ __forceinline__ void spin_bk(const int* p, int tgt) {
    if (ld_acq(p) >= tgt) return;
    while (ld_acq(p) < tgt) __nanosleep(64);
}
__device__ __forceinline__ void done_release(int* p) {
    asm volatile("red.release.gpu.global.add.s32 [%0], %1;"
                 :: "l"(__cvta_generic_to_global(p)), "r"(1) : "memory");
}
__device__ __forceinline__ float tanh_fast(float x) {
    float y;
    asm("tanh.approx.f32 %0, %1;" : "=f"(y) : "f"(x));
    return y;
}

// ---------------- pack / init ----------------
__global__ void pack_kernel(const float* __restrict__ Wf, const float* __restrict__ bf,
                            const float* __restrict__ Wi, const float* __restrict__ bi,
                            const float* __restrict__ Wo, const float* __restrict__ bo,
                            const float* __restrict__ Wg, const float* __restrict__ bg) {
    int idx = blockIdx.x * blockDim.x + threadIdx.x;
    if (idx < NG * KTOT) {
        int n = idx / KTOT;
        int k = idx % KTOT;
        int g = n >> 9, h = n & 511;
        const float* W = (g == 0) ? Wf : (g == 1) ? Wi : (g == 2) ? Wo : Wg;
        d_Wh[idx] = __float2half(W[k * H_DIM + h]);
    }
    if (idx < NG) {
        int g = idx / H_DIM, h = idx % H_DIM;
        const float* bb = (g == 0) ? bf : (g == 1) ? bi : (g == 2) ? bo : bg;
        d_Bcat[idx] = bb[h];
    }
}

__global__ void init_kernel() {
    int i = blockIdx.x * blockDim.x + threadIdx.x;
    if (i < P_INT * B_DIM * H_DIM) d_Hh[i] = __float2half(0.0f);
    if (i < NMT_MAX) { d_gemmdone[i] = 0; d_pwdone[i] = 0; }
    if (i < P_INT) { d_vflag[i] = 0; d_gchain[i] = 0; }
    if (i < NW) d_xcdone[i] = 0;
    if (i == 0) d_qhead = 0;
}

// ---------------- stage loader ----------------
__device__ __forceinline__ void load_stage(uint32_t sa, uint32_t sbB, int tid, int ch,
                                           const __half* Xb, const __half* Hb, const __half* Wb) {
    const int k0 = ch * BK;
    const __half* asrc;
    int astride;
    if (k0 < F_DIM) { asrc = Xb + k0;           astride = F_DIM; }
    else            { asrc = Hb + (k0 - F_DIM); astride = H_DIM; }
    #pragma unroll
    for (int i = 0; i < 4; i++) {
        int cell = tid + i * 256;
        int r = cell >> 3, c = cell & 7;
        cpasync16(sa + r * 128 + ((c ^ (r & 7)) * 16),
                  asrc + (size_t)r * astride + c * 8);
    }
    #pragma unroll
    for (int i = 0; i < 4; i++) {
        int cell = tid + i * 256;
        int r = cell >> 3, c = cell & 7;
        cpasync16(sbB + r * 128 + ((c ^ (r & 7)) * 16),
                  Wb + (size_t)r * KTOT + k0 + c * 8);
    }
}

// ---------------- warp softmax over 512 values (16 per lane) ----------------
__device__ __forceinline__ void softmax16(float* s) {
    float mx = -1e30f;
    #pragma unroll
    for (int q = 0; q < 16; q++) mx = fmaxf(mx, s[q]);
    #pragma unroll
    for (int o = 16; o > 0; o >>= 1) mx = fmaxf(mx, __shfl_xor_sync(0xffffffffu, mx, o));
    float sum = 0.0f;
    #pragma unroll
    for (int q = 0; q < 16; q++) { s[q] = __expf(s[q] - mx); sum += s[q]; }
    #pragma unroll
    for (int o = 16; o > 0; o >>= 1) sum += __shfl_xor_sync(0xffffffffu, sum, o);
    const float inv = 1.0f / sum;
    #pragma unroll
    for (int q = 0; q < 16; q++) s[q] *= inv;
}
// element q of lane l <-> column (q>>1)*64 + l*2 + (q&1)
__device__ __forceinline__ void load_gate16(const __half2* base, int l, float* s) {
    #pragma unroll
    for (int q2 = 0; q2 < 8; q2++) {
        float2 v = __half22float2(base[q2 * 32 + l]);
        s[2 * q2] = v.x;
        s[2 * q2 + 1] = v.y;
    }
}

// ---------------- persistent fused kernel ----------------
__global__ void __launch_bounds__(256, 2) persist(const float* __restrict__ x,
                                                  float* __restrict__ out) {
    extern __shared__ char smem[];
    const int G = gridDim.x;
    const int tid = threadIdx.x;

    if ((int)blockIdx.x == G - 1) {
        // ===== chain CTA: one warp, register-resident v across ALL waves =====
        if (tid >= 32) return;
        const int l = tid;
        float v[16];
        #pragma unroll
        for (int q = 0; q < 16; q++) v[q] = 0.0f;

        for (int w = 0; w < NW; w++) {
            const int t0 = w * P_INT;
            const int ns = (T_LEN - t0 < P_INT) ? (T_LEN - t0) : P_INT;
            const __half2* Sb2 = (const __half2*)(d_Sbuf + (size_t)(w & 1) * WAVE_S);
            float* Vb = d_Vbuf + (w & 1) * P_INT * H_DIM;
            for (int j = 0; j < ns; j++) {
                if (w >= 2 && l < 4) spin_hot(&d_pwdone[4 * j + l], 16 * (w - 1));
                __syncwarp();
                #pragma unroll
                for (int q2 = 0; q2 < 8; q2++)
                    *(float2*)(Vb + j * H_DIM + q2 * 64 + l * 2) =
                        make_float2(v[2 * q2], v[2 * q2 + 1]);
                __threadfence();
                __syncwarp();
                if (l == 0)
                    asm volatile("st.release.gpu.s32 [%0], %1;"
                                 :: "l"(d_vflag + j), "r"(w + 1) : "memory");
                spin_hot(&d_gchain[j], 12 * (w + 1));   // f,i,g tiles of feeder mtile
                const int r = (t0 + j + 1) % P_INT;
                const __half2* S = Sb2 + (((size_t)(j * B_DIM + r) * NG) >> 1);
                float sf[16], si[16], sg[16];
                load_gate16(S, l, sf);
                load_gate16(S + (H_DIM >> 1), l, si);
                load_gate16(S + ((3 * H_DIM) >> 1), l, sg);
                softmax16(sf);
                softmax16(si);
                #pragma unroll
                for (int q = 0; q < 16; q++)
                    v[q] = tanh_fast(sf[q] * v[q] + si[q] * tanh_fast(sg[q]));
            }
        }
        return;
    }

    // ===== worker CTA: global task queue =====
    __shared__ int s_task;
    const uint32_t sb = smem_u32(smem);
    const int wid = tid >> 5;
    const int l   = tid & 31;
    const int wm = (wid >> 2) * 64;
    const int wn = (wid & 3) * 32;
    const int lrow = l & 15;
    const int lk   = l >> 4;

    uint32_t sA[STG], sBs[STG];
    #pragma unroll
    for (int s = 0; s < STG; s++) {
        sA[s]  = sb + s * (A_SZ + B_SZ);
        sBs[s] = sA[s] + A_SZ;
    }

    while (true) {
        __syncthreads();
        if (tid == 0) s_task = atomicAdd(&d_qhead, 1);
        __syncthreads();
        const int task = s_task;
        if (task >= TOTAL_TASKS) break;

        // ---- conv task: 256 X rows -> fp16 ----
        if (task < NCONV) {
            const int i = task;
            const float4* src = (const float4*)x + (size_t)i * 16384;
            __half2* dst = (__half2*)d_Xh + (size_t)i * 32768;
            #pragma unroll 4
            for (int k = tid; k < 16384; k += 256) {
                float4 vv = src[k];
                dst[2 * k]     = __floats2half2_rn(vv.x, vv.y);
                dst[2 * k + 1] = __floats2half2_rn(vv.z, vv.w);
            }
            __syncthreads();
            if (tid == 0) done_release(&d_xcdone[i / 24]);   // i/24 = wave (512->21 for last 8)
            continue;
        }
        const int t2 = task - NCONV;

        int w, r, ns, ntile;
        bool is_gemm;
        int mtile = 0, nt = 0, pwb = 0;
        if (t2 < FULL_TASKS) {
            w = t2 / 1536; r = t2 % 1536; ns = 12; ntile = 768;
            if (r < ntile) {
                is_gemm = true;
                const int grp = ns * 16;
                mtile = ((r % grp) >> 4) * 4 + r / grp;
                nt = c_ntord[r & 15];
            } else {
                is_gemm = false;
                pwb = r - ntile;
            }
        } else {
            w = 21; r = t2 - FULL_TASKS; ns = 4;
            if (r < LAST_GEMM) {
                is_gemm = true;
                mtile = c_lastmt[r >> 4];
                nt = c_ntord[r & 15];
            } else {
                is_gemm = false;
                pwb = 192 + (r - LAST_GEMM);   // only j==3 blocks
            }
        }
        const int t0 = w * P_INT;
        __half* Sb = d_Sbuf + (size_t)(w & 1) * WAVE_S;

        if (is_gemm) {
            const int n0 = nt * BN;
            const int m0 = mtile * BM;
            const __half* Xb = d_Xh + ((size_t)t0 * B_DIM + m0) * F_DIM;
            const __half* Hb = d_Hh + (size_t)m0 * H_DIM;
            const __half* Wb = d_Wh + (size_t)n0 * KTOT;

            // x rows of this wave must be converted
            if (tid == 0) spin_bk(&d_xcdone[w], (w == 21) ? 8 : 24);
            __syncthreads();

            float acc[4][4][4];
            #pragma unroll
            for (int i = 0; i < 4; i++)
                #pragma unroll
                for (int j = 0; j < 4; j++)
                    #pragma unroll
                    for (int q = 0; q < 4; q++) acc[i][j][q] = 0.0f;

            #pragma unroll
            for (int c = 0; c < STG - 1; c++) {
                load_stage(sA[c], sBs[c], tid, c, Xb, Hb, Wb);
                asm volatile("cp.async.commit_group;" ::: "memory");
            }

            for (int ch = 0; ch < NCH; ch++) {
                asm volatile("cp.async.wait_group 1;" ::: "memory");
                __syncthreads();
                const int cl = ch + STG - 1;
                if (cl == 4)
                    spin_bk(&d_pwdone[mtile], 16 * w);
                if (cl < NCH)
                    load_stage(sA[cl % STG], sBs[cl % STG], tid, cl, Xb, Hb, Wb);
                asm volatile("cp.async.commit_group;" ::: "memory");

                const int s = ch % STG;
                #pragma unroll
                for (int kk = 0; kk < BK / 16; kk++) {
                    uint32_t af[4][4], bfr[2][4];
                    #pragma unroll
                    for (int mi = 0; mi < 4; mi++) {
                        int rr = wm + mi * 16 + lrow;
                        int cc = kk * 2 + lk;
                        ldm4(af[mi], sA[s] + rr * 128 + ((cc ^ (rr & 7)) * 16));
                    }
                    #pragma unroll
                    for (int bj = 0; bj < 2; bj++) {
                        int rr = wn + bj * 16 + lrow;
                        int cc = kk * 2 + lk;
                        ldm4(bfr[bj], sBs[s] + rr * 128 + ((cc ^ (rr & 7)) * 16));
                    }
                    #pragma unroll
                    for (int mi = 0; mi < 4; mi++)
                        #pragma unroll
                        for (int nj = 0; nj < 4; nj++)
                            mma16816(acc[mi][nj], af[mi],
                                     bfr[nj >> 1][nj & 1], bfr[nj >> 1][(nj & 1) + 2]);
                }
            }

            __half2* S2 = (__half2*)Sb;
            #pragma unroll
            for (int mi = 0; mi < 4; mi++) {
                #pragma unroll
                for (int nj = 0; nj < 4; nj++) {
                    int m = m0 + wm + mi * 16 + (l >> 2);
                    int n = n0 + wn + nj * 8 + (l & 3) * 2;
                    float b0 = d_Bcat[n], b1 = d_Bcat[n + 1];
                    S2[((size_t)m * NG + n) >> 1] =
                        __floats2half2_rn(acc[mi][nj][0] + b0, acc[mi][nj][1] + b1);
                    S2[((size_t)(m + 8) * NG + n) >> 1] =
                        __floats2half2_rn(acc[mi][nj][2] + b0, acc[mi][nj][3] + b1);
                }
            }
            __syncthreads();
            if (tid == 0) {
                if ((mtile & 3) == 0 && (nt < 8 || nt >= 12))
                    done_release(&d_gchain[mtile >> 2]);
                done_release(&d_gemmdone[mtile]);
            }
        } else {
            // ---- pointwise block: 8 rows, warp per row ----
            const int b = pwb;
            const int mt = b >> 4;
            const int j  = b >> 6;
            if (tid == 0) spin_bk(&d_gemmdone[mt], 16 * (w + 1));
            __syncthreads();

            const int m = b * 8 + wid;
            const float* Vb = d_Vbuf + (w & 1) * P_INT * H_DIM;
            const __half2* S = (const __half2*)Sb + (((size_t)m * NG) >> 1);
            float sf[16], si[16], so[16], sg[16];
            load_gate16(S, l, sf);
            load_gate16(S + (H_DIM >> 1), l, si);
            load_gate16(S + ((2 * H_DIM) >> 1), l, so);
            load_gate16(S + ((3 * H_DIM) >> 1), l, sg);
            softmax16(sf);
            softmax16(si);
            softmax16(so);

            if (tid == 0) spin_bk(&d_vflag[j], w + 1);
            __syncthreads();

            __half2* Hh2 = (__half2*)d_Hh;
            const bool wout = (j == 3);
            #pragma unroll
            for (int q2 = 0; q2 < 8; q2++) {
                float2 vv = *(const float2*)(Vb + j * H_DIM + q2 * 64 + l * 2);
                float c0 = tanh_fast(sf[2 * q2] * vv.x + si[2 * q2] * tanh_fast(sg[2 * q2]));
                float c1 = tanh_fast(sf[2 * q2 + 1] * vv.y + si[2 * q2 + 1] * tanh_fast(sg[2 * q2 + 1]));
                float h0 = so[2 * q2] * c0;
                float h1 = so[2 * q2 + 1] * c1;
                Hh2[((size_t)m * H_DIM + q2 * 64 + l * 2) >> 1] = __floats2half2_rn(h0, h1);
                if (wout)
                    *(float2*)(out + (size_t)(m & 511) * H_DIM + q2 * 64 + l * 2) =
                        make_float2(h0, h1);
            }
            __syncthreads();
            if (tid == 0) done_release(&d_pwdone[mt]);
        }
    }
}

// ---------------- launch ----------------
extern "C" void kernel_launch(void* const* d_in, const int* in_sizes, int n_in,
                              void* d_out, int out_size) {
    const float* x  = (const float*)d_in[0];
    const float* Wf = (const float*)d_in[1];
    const float* bf = (const float*)d_in[2];
    const float* Wi = (const float*)d_in[3];
    const float* bi = (const float*)d_in[4];
    const float* Wo = (const float*)d_in[5];
    const float* bo = (const float*)d_in[6];
    const float* Wg = (const float*)d_in[7];
    const float* bg = (const float*)d_in[8];
    float* out = (float*)d_out;

    cudaFuncSetAttribute(persist, cudaFuncAttributeMaxDynamicSharedMemorySize, SMEM_BYTES);

    int sms = 0, occ = 0;
    cudaDeviceGetAttribute(&sms, cudaDevAttrMultiProcessorCount, 0);
    cudaOccupancyMaxActiveBlocksPerMultiprocessor(&occ, persist, 256, SMEM_BYTES);
    if (occ < 1) occ = 1;
    int G = occ * sms;
    if (G > 297) G = 297;
    if (G < 2) G = 2;

    {
        int n = NG * KTOT;
        pack_kernel<<<(n + 255) / 256, 256>>>(Wf, bf, Wi, bi, Wo, bo, Wg, bg);
    }
    {
        int n = P_INT * B_DIM * H_DIM;
        init_kernel<<<(n + 255) / 256, 256>>>();
    }

    persist<<<G, 256, SMEM_BYTES>>>(x, out);
}